// round 13
// baseline (speedup 1.0000x reference)
#include <cuda_runtime.h>
#include <cuda_bf16.h>
#include <cstdint>
#include <math.h>

#define BATCH 8
#define SEQ 128
#define DIM 512
#define NHEAD 8
#define HDIM 64
#define NLAYER 2
#define NSTEPS 20
#define DFF 1024
#define NOUT 1000
#define NROWS (BATCH*SEQ)

typedef __nv_bfloat16 bf16;

// ---------------- scratch ----------------
__device__ float g_xemb[NROWS*DIM];
__device__ float g_h   [NROWS*DIM];
__device__ float g_q   [NROWS*DIM];
__device__ float g_k   [NROWS*DIM];
__device__ float g_v   [NROWS*DIM];
__device__ float g_hmean[BATCH*DIM];
__device__ __align__(16) bf16 g_hn_hi [NROWS*DIM];
__device__ __align__(16) bf16 g_hn_lo [NROWS*DIM];
__device__ __align__(16) bf16 g_o_hi  [NROWS*DIM];
__device__ __align__(16) bf16 g_o_lo  [NROWS*DIM];
__device__ __align__(16) bf16 g_mid_hi[NROWS*DFF];
__device__ __align__(16) bf16 g_mid_lo[NROWS*DFF];

#define WOFF_Q 0
#define WOFF_K (DIM*DIM)
#define WOFF_V (2*DIM*DIM)
#define WOFF_O (3*DIM*DIM)
#define WOFF_1 (4*DIM*DIM)
#define WOFF_2 (4*DIM*DIM + DFF*DIM)
#define WLAYER (4*DIM*DIM + 2*DFF*DIM)
__device__ __align__(16) bf16 g_wh[NLAYER*WLAYER];
__device__ __align__(16) bf16 g_wl[NLAYER*WLAYER];

// ---------------- helpers ----------------
__device__ __forceinline__ uint32_t smem_u32(const void* p){
    uint32_t a;
    asm("{ .reg .u64 t; cvta.to.shared.u64 t, %1; cvt.u32.u64 %0, t; }" : "=r"(a) : "l"(p));
    return a;
}
#define CP16(sa, gp) \
    asm volatile("cp.async.cg.shared.global [%0], [%1], 16;" :: "r"(sa), "l"(gp))
#define CP_COMMIT() asm volatile("cp.async.commit_group;" ::: "memory")
#define CP_WAIT1()  asm volatile("cp.async.wait_group 1;" ::: "memory")

#define LDMX4(r, addr) \
    asm volatile("ldmatrix.sync.aligned.m8n8.x4.shared.b16 {%0,%1,%2,%3}, [%4];" \
        : "=r"((r)[0]), "=r"((r)[1]), "=r"((r)[2]), "=r"((r)[3]) : "r"(addr))

__device__ __forceinline__ void mma16816(float* c, const uint32_t* a, const uint32_t* b){
    asm volatile("mma.sync.aligned.m16n8k16.row.col.f32.bf16.bf16.f32 "
        "{%0,%1,%2,%3}, {%4,%5,%6,%7}, {%8,%9}, {%0,%1,%2,%3};"
        : "+f"(c[0]), "+f"(c[1]), "+f"(c[2]), "+f"(c[3])
        : "r"(a[0]), "r"(a[1]), "r"(a[2]), "r"(a[3]), "r"(b[0]), "r"(b[1]));
}

__device__ __forceinline__ void split2(float v, unsigned short& hb, unsigned short& lb){
    bf16 h = __float2bfloat16(v);
    bf16 l = __float2bfloat16(v - __bfloat162float(h));
    hb = __bfloat16_as_ushort(h);
    lb = __bfloat16_as_ushort(l);
}
__device__ __forceinline__ float warp_sum(float v){
    #pragma unroll
    for (int o = 16; o > 0; o >>= 1) v += __shfl_xor_sync(0xffffffffu, v, o);
    return v;
}

// ---------------- weight transpose + split (12 jobs, one launch) ------------
struct WJob { const float* W; bf16* hi; bf16* lo; int K; int N; };
struct WJobs { WJob j[12]; };

__global__ void wsplit_multi(WJobs jobs)
{
    __shared__ float t[32][33];
    const WJob jb = jobs.j[blockIdx.z];
    const int K = jb.K, N = jb.N;
    int nb = blockIdx.x*32, kb = blockIdx.y*32;
    if (nb >= N || kb >= K) return;
    int nx = nb + threadIdx.x;
    #pragma unroll
    for (int r = 0; r < 4; r++) {
        int k = kb + threadIdx.y + r*8;
        t[threadIdx.y + r*8][threadIdx.x] = jb.W[(size_t)k*N + nx];
    }
    __syncthreads();
    int k2 = kb + threadIdx.x;
    #pragma unroll
    for (int r = 0; r < 4; r++) {
        int n2 = nb + threadIdx.y + r*8;
        unsigned short hb, lb;
        split2(t[threadIdx.x][threadIdx.y + r*8], hb, lb);
        jb.hi[(size_t)n2*K + k2] = __ushort_as_bfloat16(hb);
        jb.lo[(size_t)n2*K + k2] = __ushort_as_bfloat16(lb);
    }
}

// ---------------- embedding + h0=0 ----------------
__global__ void embed_kernel(const int* __restrict__ x,
                             const float* __restrict__ tok,
                             const float* __restrict__ pos)
{
    int row = blockIdx.x;
    int s = row % SEQ;
    int t = x[row];
    int d = threadIdx.x * 4;
    float4 tv = *(const float4*)(tok + (size_t)t*DIM + d);
    float4 pv = *(const float4*)(pos + (size_t)s*DIM + d);
    *(float4*)&g_xemb[(size_t)row*DIM + d] = make_float4(tv.x+pv.x, tv.y+pv.y, tv.z+pv.z, tv.w+pv.w);
    *(float4*)&g_h   [(size_t)row*DIM + d] = make_float4(0.f,0.f,0.f,0.f);
}

// ---------------- layernorm, fused bf16-split output ----------------
__global__ void ln_split_kernel(const float* __restrict__ in,
                                const float* __restrict__ gamma,
                                const float* __restrict__ beta,
                                bf16* __restrict__ oh, bf16* __restrict__ ol)
{
    int row = blockIdx.x;
    int tid = threadIdx.x;   // 128
    int d = tid * 4;
    float4 v = *(const float4*)(in + (size_t)row*DIM + d);
    float s  = v.x + v.y + v.z + v.w;
    float sq = v.x*v.x + v.y*v.y + v.z*v.z + v.w*v.w;
    s = warp_sum(s); sq = warp_sum(sq);
    __shared__ float red[8]; __shared__ float mb[2];
    int w = tid >> 5, lane = tid & 31;
    if (lane == 0) { red[w] = s; red[4+w] = sq; }
    __syncthreads();
    if (tid == 0) {
        float S = red[0]+red[1]+red[2]+red[3];
        float Q = red[4]+red[5]+red[6]+red[7];
        float mu = S * (1.f/DIM);
        mb[0] = mu;
        mb[1] = rsqrtf(Q*(1.f/DIM) - mu*mu + 1e-5f);
    }
    __syncthreads();
    float mu = mb[0], inv = mb[1];
    float4 g4 = *(const float4*)(gamma + d);
    float4 b4 = *(const float4*)(beta + d);
    float r0 = (v.x-mu)*inv*g4.x + b4.x;
    float r1 = (v.y-mu)*inv*g4.y + b4.y;
    float r2 = (v.z-mu)*inv*g4.z + b4.z;
    float r3 = (v.w-mu)*inv*g4.w + b4.w;
    unsigned short hb[4], lb[4];
    split2(r0,hb[0],lb[0]); split2(r1,hb[1],lb[1]);
    split2(r2,hb[2],lb[2]); split2(r3,hb[3],lb[3]);
    uint2 hp, lp;
    hp.x = hb[0] | ((uint32_t)hb[1] << 16); hp.y = hb[2] | ((uint32_t)hb[3] << 16);
    lp.x = lb[0] | ((uint32_t)lb[1] << 16); lp.y = lb[2] | ((uint32_t)lb[3] << 16);
    *(uint2*)&oh[(size_t)row*DIM + d] = hp;
    *(uint2*)&ol[(size_t)row*DIM + d] = lp;
}

// ---------------- mma.sync GEMM, 64x64 tile, 128 thr, 3-stage pipeline ------
struct GemmSet {
    const bf16* wh; const bf16* wl;
    const float* bias;
    float* out;
    bf16* oh; bf16* ol;
};
struct GemmArgs { GemmSet s[3]; };

#define KS      40
#define TILE_E  (64*KS)
#define TILE_B  (TILE_E*2)         // 5120 bytes
#define STAGE_B (4*TILE_B)         // Ah, Al, Bh, Bl = 20480
#define NSTAGE  3
#define GEMM_SMEM (NSTAGE*STAGE_B) // 61440

template<int EPI>
__global__ void __launch_bounds__(128)
mma_gemm(const bf16* __restrict__ a_hi, const bf16* __restrict__ a_lo,
         GemmArgs args, int M, int N, int K)
{
    extern __shared__ char smem[];
    const GemmSet gs = args.s[blockIdx.z];
    const int m0 = blockIdx.y * 64;
    const int n0 = blockIdx.x * 64;
    const int tid = threadIdx.x;
    const uint32_t sbase = smem_u32(smem);

    const int lrow = tid >> 1;
    const int lke  = (tid & 1) * 16;
    const bf16* gAh = a_hi  + (size_t)(m0 + lrow)*K + lke;
    const bf16* gAl = a_lo  + (size_t)(m0 + lrow)*K + lke;
    const bf16* gBh = gs.wh + (size_t)(n0 + lrow)*K + lke;
    const bf16* gBl = gs.wl + (size_t)(n0 + lrow)*K + lke;
    const uint32_t sA = sbase + (uint32_t)(lrow*KS + lke)*2;

    auto load_stage = [&](int st, int kt){
        uint32_t b = sA + st*STAGE_B;
        const bf16* p0 = gAh + kt;
        const bf16* p1 = gAl + kt;
        const bf16* p2 = gBh + kt;
        const bf16* p3 = gBl + kt;
        CP16(b,               p0); CP16(b + 16,             p0 + 8);
        CP16(b + TILE_B,      p1); CP16(b + TILE_B + 16,    p1 + 8);
        CP16(b + 2*TILE_B,    p2); CP16(b + 2*TILE_B + 16,  p2 + 8);
        CP16(b + 3*TILE_B,    p3); CP16(b + 3*TILE_B + 16,  p3 + 8);
        CP_COMMIT();
    };

    const int w  = tid >> 5, l = tid & 31;
    const int wr = (w & 1) * 32;
    const int wc = (w >> 1) * 32;

    const uint32_t aoff = (uint32_t)(((wr + (l & 15))*KS + (l >> 4)*8) * 2);
    const uint32_t boff = (uint32_t)(((wc + (l >> 4)*8 + (l & 7))*KS + ((l >> 3) & 1)*8) * 2);

    float c[2][4][4];
    #pragma unroll
    for (int i = 0; i < 2; i++)
        #pragma unroll
        for (int j = 0; j < 4; j++)
            #pragma unroll
            for (int r = 0; r < 4; r++) c[i][j][r] = 0.f;

    const int KT = K / 32;
    load_stage(0, 0);
    load_stage(1, 32);
    int s_cur = 0, s_load = 2;
    for (int kt = 0; kt < KT; kt++) {
        CP_WAIT1();                      // stage kt complete (1 group may remain)
        __syncthreads();
        if (kt + 2 < KT) {
            load_stage(s_load, (kt + 2) * 32);
            s_load = (s_load == NSTAGE-1) ? 0 : s_load + 1;
        } else {
            CP_COMMIT();                 // empty group keeps wait counting exact
        }

        const uint32_t stb = sbase + s_cur*STAGE_B;
        s_cur = (s_cur == NSTAGE-1) ? 0 : s_cur + 1;

        #pragma unroll
        for (int ks = 0; ks < 2; ks++) {
            const uint32_t kb = stb + ks*32;
            uint32_t ah[2][4], al[2][4], bb_h[4], bb_h2[4], bb_l[4], bb_l2[4];
            LDMX4(ah[0], kb + aoff);
            LDMX4(ah[1], kb + aoff + 16*KS*2);
            LDMX4(al[0], kb + TILE_B + aoff);
            LDMX4(al[1], kb + TILE_B + aoff + 16*KS*2);
            LDMX4(bb_h,  kb + 2*TILE_B + boff);
            LDMX4(bb_h2, kb + 2*TILE_B + boff + 16*KS*2);
            LDMX4(bb_l,  kb + 3*TILE_B + boff);
            LDMX4(bb_l2, kb + 3*TILE_B + boff + 16*KS*2);

            uint32_t bh[4][2] = {{bb_h[0],bb_h[1]},{bb_h[2],bb_h[3]},
                                 {bb_h2[0],bb_h2[1]},{bb_h2[2],bb_h2[3]}};
            uint32_t bl[4][2] = {{bb_l[0],bb_l[1]},{bb_l[2],bb_l[3]},
                                 {bb_l2[0],bb_l2[1]},{bb_l2[2],bb_l2[3]}};
            #pragma unroll
            for (int i = 0; i < 2; i++)
                #pragma unroll
                for (int j = 0; j < 4; j++) {
                    mma16816(c[i][j], ah[i], bh[j]);
                    mma16816(c[i][j], ah[i], bl[j]);
                    mma16816(c[i][j], al[i], bh[j]);
                }
        }
        __syncthreads();
    }

    const int fr = l >> 2;
    const int fc = (l & 3) * 2;
    #pragma unroll
    for (int i = 0; i < 2; i++) {
        #pragma unroll
        for (int j = 0; j < 4; j++) {
            const int cc = n0 + wc + j*8 + fc;
            float2 bv = *(const float2*)(gs.bias + cc);
            #pragma unroll
            for (int hh = 0; hh < 2; hh++) {
                const int row = m0 + wr + i*16 + fr + hh*8;
                float v0 = c[i][j][hh*2 + 0] + bv.x;
                float v1 = c[i][j][hh*2 + 1] + bv.y;
                if (EPI == 0) {
                    *(float2*)(gs.out + (size_t)row*N + cc) = make_float2(v0, v1);
                } else if (EPI == 1) {
                    float2* cp = (float2*)(gs.out + (size_t)row*N + cc);
                    float2 o = *cp;
                    o.x += v0; o.y += v1;
                    *cp = o;
                } else if (EPI == 2) {
                    unsigned short h0, l0, h1, l1;
                    split2(fmaxf(v0, 0.f), h0, l0);
                    split2(fmaxf(v1, 0.f), h1, l1);
                    *(uint32_t*)(gs.oh + (size_t)row*N + cc) = (uint32_t)h0 | ((uint32_t)h1 << 16);
                    *(uint32_t*)(gs.ol + (size_t)row*N + cc) = (uint32_t)l0 | ((uint32_t)l1 << 16);
                } else {
                    float2* cp = (float2*)(gs.out + (size_t)row*N + cc);
                    float2 h2 = *cp;
                    float2 xe = *(const float2*)&g_xemb[(size_t)row*DIM + cc];
                    h2.x = h2.x + 0.5f*(tanhf(h2.x + v0 + xe.x) - h2.x);
                    h2.y = h2.y + 0.5f*(tanhf(h2.y + v1 + xe.y) - h2.y);
                    *cp = h2;
                }
            }
        }
    }
}

// ---------------- attention: CTA = (qblock64, head, batch), 256 thr ---------
#define QB 64
#define QV_PAD 68
#define KT_PAD 132
#define SMEM_ATTN ((QB*QV_PAD + HDIM*KT_PAD + SEQ*QV_PAD + QB*KT_PAD) * (int)sizeof(float))

__global__ void __launch_bounds__(256)
attn_kernel()
{
    extern __shared__ float sm[];
    float* Qs = sm;                      // [64][68]
    float* Kt = Qs + QB*QV_PAD;          // [64][132]
    float* Vs = Kt + HDIM*KT_PAD;        // [128][68]
    float* Ps = Vs + SEQ*QV_PAD;         // [64][132]

    const int qb   = blockIdx.x;
    const int head = blockIdx.y;
    const int b    = blockIdx.z;
    const int tid  = threadIdx.x;

    const float* qg = g_q + (size_t)(b*SEQ + qb*QB)*DIM + head*HDIM;
    const float* kg = g_k + (size_t)(b*SEQ)*DIM + head*HDIM;
    const float* vg = g_v + (size_t)(b*SEQ)*DIM + head*HDIM;

    #pragma unroll
    for (int it = 0; it < 4; it++) {
        int idx = it*256 + tid;
        int s = idx >> 4, d4 = (idx & 15)*4;
        *(float4*)&Qs[s*QV_PAD + d4] = *(const float4*)(qg + (size_t)s*DIM + d4);
    }
    #pragma unroll
    for (int it = 0; it < 8; it++) {
        int idx = it*256 + tid;
        int s = idx >> 4, d4 = (idx & 15)*4;
        *(float4*)&Vs[s*QV_PAD + d4] = *(const float4*)(vg + (size_t)s*DIM + d4);
        float4 kv = *(const float4*)(kg + (size_t)s*DIM + d4);
        Kt[(d4+0)*KT_PAD + s] = kv.x;
        Kt[(d4+1)*KT_PAD + s] = kv.y;
        Kt[(d4+2)*KT_PAD + s] = kv.z;
        Kt[(d4+3)*KT_PAD + s] = kv.w;
    }
    __syncthreads();

    {
        const int i0 = (tid >> 4)*4;
        const int j0 = (tid & 15)*8;
        float acc[4][8];
        #pragma unroll
        for (int i=0;i<4;i++)
            #pragma unroll
            for (int j=0;j<8;j++) acc[i][j] = 0.f;
        for (int d = 0; d < HDIM; d++) {
            float q0 = Qs[(i0+0)*QV_PAD + d];
            float q1 = Qs[(i0+1)*QV_PAD + d];
            float q2 = Qs[(i0+2)*QV_PAD + d];
            float q3 = Qs[(i0+3)*QV_PAD + d];
            float4 k0 = *(float4*)&Kt[d*KT_PAD + j0];
            float4 k1 = *(float4*)&Kt[d*KT_PAD + j0 + 4];
            float kk[8] = {k0.x,k0.y,k0.z,k0.w,k1.x,k1.y,k1.z,k1.w};
            #pragma unroll
            for (int j=0;j<8;j++) {
                acc[0][j] = fmaf(q0, kk[j], acc[0][j]);
                acc[1][j] = fmaf(q1, kk[j], acc[1][j]);
                acc[2][j] = fmaf(q2, kk[j], acc[2][j]);
                acc[3][j] = fmaf(q3, kk[j], acc[3][j]);
            }
        }
        const float sc = 0.125f;
        #pragma unroll
        for (int i=0;i<4;i++) {
            *(float4*)&Ps[(i0+i)*KT_PAD + j0] =
                make_float4(acc[i][0]*sc, acc[i][1]*sc, acc[i][2]*sc, acc[i][3]*sc);
            *(float4*)&Ps[(i0+i)*KT_PAD + j0 + 4] =
                make_float4(acc[i][4]*sc, acc[i][5]*sc, acc[i][6]*sc, acc[i][7]*sc);
        }
    }
    __syncthreads();

    {
        const int w = tid >> 5, lane = tid & 31;
        #pragma unroll
        for (int rr = 0; rr < 8; rr++) {
            float* pr = &Ps[(w*8 + rr)*KT_PAD];
            float mx = -1e30f;
            #pragma unroll
            for (int u = 0; u < 4; u++) mx = fmaxf(mx, pr[lane + 32*u]);
            #pragma unroll
            for (int o = 16; o > 0; o >>= 1) mx = fmaxf(mx, __shfl_xor_sync(0xffffffffu, mx, o));
            float sum = 0.f;
            #pragma unroll
            for (int u = 0; u < 4; u++) {
                float e = __expf(pr[lane + 32*u] - mx);
                pr[lane + 32*u] = e;
                sum += e;
            }
            sum = warp_sum(sum);
            float inv = 1.f / sum;
            #pragma unroll
            for (int u = 0; u < 4; u++) pr[lane + 32*u] *= inv;
        }
    }
    __syncthreads();

    {
        const int r0 = (tid >> 4)*4;
        const int c0 = (tid & 15)*4;
        float oa[4][4];
        #pragma unroll
        for (int i=0;i<4;i++)
            #pragma unroll
            for (int j=0;j<4;j++) oa[i][j] = 0.f;
        const float* pr0 = &Ps[(r0+0)*KT_PAD];
        const float* pr1 = &Ps[(r0+1)*KT_PAD];
        const float* pr2 = &Ps[(r0+2)*KT_PAD];
        const float* pr3 = &Ps[(r0+3)*KT_PAD];
        for (int kk = 0; kk < SEQ; kk++) {
            float4 vv = *(float4*)&Vs[kk*QV_PAD + c0];
            float p0 = pr0[kk], p1 = pr1[kk], p2 = pr2[kk], p3 = pr3[kk];
            oa[0][0]=fmaf(p0,vv.x,oa[0][0]); oa[0][1]=fmaf(p0,vv.y,oa[0][1]);
            oa[0][2]=fmaf(p0,vv.z,oa[0][2]); oa[0][3]=fmaf(p0,vv.w,oa[0][3]);
            oa[1][0]=fmaf(p1,vv.x,oa[1][0]); oa[1][1]=fmaf(p1,vv.y,oa[1][1]);
            oa[1][2]=fmaf(p1,vv.z,oa[1][2]); oa[1][3]=fmaf(p1,vv.w,oa[1][3]);
            oa[2][0]=fmaf(p2,vv.x,oa[2][0]); oa[2][1]=fmaf(p2,vv.y,oa[2][1]);
            oa[2][2]=fmaf(p2,vv.z,oa[2][2]); oa[2][3]=fmaf(p2,vv.w,oa[2][3]);
            oa[3][0]=fmaf(p3,vv.x,oa[3][0]); oa[3][1]=fmaf(p3,vv.y,oa[3][1]);
            oa[3][2]=fmaf(p3,vv.z,oa[3][2]); oa[3][3]=fmaf(p3,vv.w,oa[3][3]);
        }
        #pragma unroll
        for (int i = 0; i < 4; i++) {
            bf16* ohg = g_o_hi + (size_t)(b*SEQ + qb*QB + r0 + i)*DIM + head*HDIM + c0;
            bf16* olg = g_o_lo + (size_t)(b*SEQ + qb*QB + r0 + i)*DIM + head*HDIM + c0;
            unsigned short hb[4], lb[4];
            #pragma unroll
            for (int j = 0; j < 4; j++) split2(oa[i][j], hb[j], lb[j]);
            uint2 hp, lp;
            hp.x = hb[0]|((uint32_t)hb[1]<<16); hp.y = hb[2]|((uint32_t)hb[3]<<16);
            lp.x = lb[0]|((uint32_t)lb[1]<<16); lp.y = lb[2]|((uint32_t)lb[3]<<16);
            *(uint2*)ohg = hp;
            *(uint2*)olg = lp;
        }
    }
}

// ---------------- mean + head ----------------
__global__ void mean_kernel()
{
    int idx = blockIdx.x*128 + threadIdx.x;
    int b = idx / DIM, d = idx % DIM;
    const float* p = g_h + (size_t)b*SEQ*DIM + d;
    float s = 0.f;
    #pragma unroll 8
    for (int ss = 0; ss < SEQ; ss++) s += p[(size_t)ss*DIM];
    g_hmean[idx] = s * (1.f/SEQ);
}

__global__ void head_kernel(const float* __restrict__ hw,
                            const float* __restrict__ hb,
                            float* __restrict__ out)
{
    int idx = blockIdx.x*128 + threadIdx.x;
    if (idx >= BATCH*NOUT) return;
    int b = idx / NOUT, o = idx % NOUT;
    const float* hm = g_hmean + b*DIM;
    float acc = hb[o];
    #pragma unroll 8
    for (int d = 0; d < DIM; d++) acc = fmaf(hm[d], hw[(size_t)d*NOUT + o], acc);
    out[idx] = acc;
}

// ---------------- host ----------------
template<int EPI>
static void launch_mma(const bf16* ah, const bf16* al, const GemmArgs& ga,
                       int M, int N, int K, int nz)
{
    dim3 grid(N/64, M/64, nz), block(128);
    mma_gemm<EPI><<<grid, block, GEMM_SMEM>>>(ah, al, ga, M, N, K);
}

extern "C" void kernel_launch(void* const* d_in, const int* in_sizes, int n_in,
                              void* d_out, int out_size)
{
    const int*   x   = (const int*)  d_in[0];
    const float* tok = (const float*)d_in[2];
    const float* pos = (const float*)d_in[3];
    const float* Wq  = (const float*)d_in[4];
    const float* bq  = (const float*)d_in[5];
    const float* Wk  = (const float*)d_in[6];
    const float* bk  = (const float*)d_in[7];
    const float* Wv  = (const float*)d_in[8];
    const float* bv  = (const float*)d_in[9];
    const float* Wo  = (const float*)d_in[10];
    const float* bo  = (const float*)d_in[11];
    const float* W1  = (const float*)d_in[12];
    const float* b1  = (const float*)d_in[13];
    const float* W2  = (const float*)d_in[14];
    const float* b2  = (const float*)d_in[15];
    const float* l1g = (const float*)d_in[16];
    const float* l1b = (const float*)d_in[17];
    const float* l2g = (const float*)d_in[18];
    const float* l2b = (const float*)d_in[19];
    const float* hw  = (const float*)d_in[20];
    const float* hb  = (const float*)d_in[21];
    float* out = (float*)d_out;

    void *p_h, *p_q, *p_k, *p_v, *p_hnh, *p_hnl, *p_oh, *p_ol, *p_mh, *p_ml, *p_wh, *p_wl;
    cudaGetSymbolAddress(&p_h,  g_h);
    cudaGetSymbolAddress(&p_q,  g_q);
    cudaGetSymbolAddress(&p_k,  g_k);
    cudaGetSymbolAddress(&p_v,  g_v);
    cudaGetSymbolAddress(&p_hnh, g_hn_hi);
    cudaGetSymbolAddress(&p_hnl, g_hn_lo);
    cudaGetSymbolAddress(&p_oh, g_o_hi);
    cudaGetSymbolAddress(&p_ol, g_o_lo);
    cudaGetSymbolAddress(&p_mh, g_mid_hi);
    cudaGetSymbolAddress(&p_ml, g_mid_lo);
    cudaGetSymbolAddress(&p_wh, g_wh);
    cudaGetSymbolAddress(&p_wl, g_wl);
    float* hB = (float*)p_h;
    bf16 *hnh = (bf16*)p_hnh, *hnl = (bf16*)p_hnl;
    bf16 *ohB = (bf16*)p_oh,  *olB = (bf16*)p_ol;
    bf16 *mhB = (bf16*)p_mh,  *mlB = (bf16*)p_ml;
    bf16 *whB = (bf16*)p_wh,  *wlB = (bf16*)p_wl;

    static bool attr_done = false;
    if (!attr_done) {
        cudaFuncSetAttribute(attn_kernel,  cudaFuncAttributeMaxDynamicSharedMemorySize, SMEM_ATTN);
        cudaFuncSetAttribute(mma_gemm<0>, cudaFuncAttributeMaxDynamicSharedMemorySize, GEMM_SMEM);
        cudaFuncSetAttribute(mma_gemm<1>, cudaFuncAttributeMaxDynamicSharedMemorySize, GEMM_SMEM);
        cudaFuncSetAttribute(mma_gemm<2>, cudaFuncAttributeMaxDynamicSharedMemorySize, GEMM_SMEM);
        cudaFuncSetAttribute(mma_gemm<3>, cudaFuncAttributeMaxDynamicSharedMemorySize, GEMM_SMEM);
        attr_done = true;
    }

    // weight transpose + split: one launch, 12 jobs
    {
        bf16* l0h = whB;          bf16* l0l = wlB;
        bf16* l1h = whB + WLAYER; bf16* l1l = wlB + WLAYER;
        WJobs wj{};
        wj.j[0]  = {Wq,           l0h + WOFF_Q, l0l + WOFF_Q, DIM, DIM};
        wj.j[1]  = {Wk,           l0h + WOFF_K, l0l + WOFF_K, DIM, DIM};
        wj.j[2]  = {Wv,           l0h + WOFF_V, l0l + WOFF_V, DIM, DIM};
        wj.j[3]  = {Wo,           l0h + WOFF_O, l0l + WOFF_O, DIM, DIM};
        wj.j[4]  = {W1,           l0h + WOFF_1, l0l + WOFF_1, DIM, DFF};
        wj.j[5]  = {W2,           l0h + WOFF_2, l0l + WOFF_2, DFF, DIM};
        wj.j[6]  = {Wq + DIM*DIM, l1h + WOFF_Q, l1l + WOFF_Q, DIM, DIM};
        wj.j[7]  = {Wk + DIM*DIM, l1h + WOFF_K, l1l + WOFF_K, DIM, DIM};
        wj.j[8]  = {Wv + DIM*DIM, l1h + WOFF_V, l1l + WOFF_V, DIM, DIM};
        wj.j[9]  = {Wo + DIM*DIM, l1h + WOFF_O, l1l + WOFF_O, DIM, DIM};
        wj.j[10] = {W1 + DIM*DFF, l1h + WOFF_1, l1l + WOFF_1, DIM, DFF};
        wj.j[11] = {W2 + DIM*DFF, l1h + WOFF_2, l1l + WOFF_2, DFF, DIM};
        wsplit_multi<<<dim3(32, 32, 12), dim3(32, 8)>>>(wj);
    }

    embed_kernel<<<NROWS, 128>>>(x, tok, pos);

    float* qkv[3] = {(float*)p_q, (float*)p_k, (float*)p_v};
    for (int st = 0; st < NSTEPS; st++) {
        for (int l = 0; l < NLAYER; l++) {
            const size_t vd = (size_t)l*DIM, vf = (size_t)l*DFF;
            bf16* lh = whB + (size_t)l*WLAYER;
            bf16* ll = wlB + (size_t)l*WLAYER;

            ln_split_kernel<<<NROWS, 128>>>(hB, l1g + vd, l1b + vd, hnh, hnl);

            GemmArgs ga{};
            ga.s[0] = {lh + WOFF_Q, ll + WOFF_Q, bq + vd, qkv[0], nullptr, nullptr};
            ga.s[1] = {lh + WOFF_K, ll + WOFF_K, bk + vd, qkv[1], nullptr, nullptr};
            ga.s[2] = {lh + WOFF_V, ll + WOFF_V, bv + vd, qkv[2], nullptr, nullptr};
            launch_mma<0>(hnh, hnl, ga, NROWS, DIM, DIM, 3);

            attn_kernel<<<dim3(SEQ/QB, NHEAD, BATCH), 256, SMEM_ATTN>>>();

            GemmArgs go{};
            go.s[0] = {lh + WOFF_O, ll + WOFF_O, bo + vd, hB, nullptr, nullptr};
            launch_mma<1>(ohB, olB, go, NROWS, DIM, DIM, 1);

            ln_split_kernel<<<NROWS, 128>>>(hB, l2g + vd, l2b + vd, hnh, hnl);

            GemmArgs g1{};
            g1.s[0] = {lh + WOFF_1, ll + WOFF_1, b1 + vf, nullptr, mhB, mlB};
            launch_mma<2>(hnh, hnl, g1, NROWS, DFF, DIM, 1);

            GemmArgs g2{};
            g2.s[0] = {lh + WOFF_2, ll + WOFF_2, b2 + vd, hB, nullptr, nullptr};
            launch_mma<3>(mhB, mlB, g2, NROWS, DIM, DFF, 1);
        }
    }

    mean_kernel<<<BATCH*DIM/128, 128>>>();
    head_kernel<<<(BATCH*NOUT + 127)/128, 128>>>(hw, hb, out);
}

// round 14
// speedup vs baseline: 1.1232x; 1.1232x over previous
#include <cuda_runtime.h>
#include <cuda_bf16.h>
#include <cstdint>
#include <math.h>

#define BATCH 8
#define SEQ 128
#define DIM 512
#define NHEAD 8
#define HDIM 64
#define NLAYER 2
#define NSTEPS 20
#define DFF 1024
#define NOUT 1000
#define NROWS (BATCH*SEQ)

typedef __nv_bfloat16 bf16;

// ---------------- scratch ----------------
__device__ float g_xemb[NROWS*DIM];
__device__ float g_h   [NROWS*DIM];
__device__ float g_q   [NROWS*DIM];
__device__ float g_k   [NROWS*DIM];
__device__ float g_v   [NROWS*DIM];
__device__ float g_hmean[BATCH*DIM];
__device__ __align__(16) bf16 g_hn_hi [NROWS*DIM];
__device__ __align__(16) bf16 g_hn_lo [NROWS*DIM];
__device__ __align__(16) bf16 g_o_hi  [NROWS*DIM];
__device__ __align__(16) bf16 g_o_lo  [NROWS*DIM];
__device__ __align__(16) bf16 g_mid_hi[NROWS*DFF];
__device__ __align__(16) bf16 g_mid_lo[NROWS*DFF];

#define WOFF_Q 0
#define WOFF_K (DIM*DIM)
#define WOFF_V (2*DIM*DIM)
#define WOFF_O (3*DIM*DIM)
#define WOFF_1 (4*DIM*DIM)
#define WOFF_2 (4*DIM*DIM + DFF*DIM)
#define WLAYER (4*DIM*DIM + 2*DFF*DIM)
__device__ __align__(16) bf16 g_wh[NLAYER*WLAYER];
__device__ __align__(16) bf16 g_wl[NLAYER*WLAYER];

// ---------------- helpers ----------------
__device__ __forceinline__ uint32_t smem_u32(const void* p){
    uint32_t a;
    asm("{ .reg .u64 t; cvta.to.shared.u64 t, %1; cvt.u32.u64 %0, t; }" : "=r"(a) : "l"(p));
    return a;
}
#define CP16(sa, gp) \
    asm volatile("cp.async.cg.shared.global [%0], [%1], 16;" :: "r"(sa), "l"(gp))
#define CP_COMMIT() asm volatile("cp.async.commit_group;" ::: "memory")
#define CP_WAIT1()  asm volatile("cp.async.wait_group 1;" ::: "memory")

#define LDMX4(r, addr) \
    asm volatile("ldmatrix.sync.aligned.m8n8.x4.shared.b16 {%0,%1,%2,%3}, [%4];" \
        : "=r"((r)[0]), "=r"((r)[1]), "=r"((r)[2]), "=r"((r)[3]) : "r"(addr))

__device__ __forceinline__ void mma16816(float* c, const uint32_t* a, const uint32_t* b){
    asm volatile("mma.sync.aligned.m16n8k16.row.col.f32.bf16.bf16.f32 "
        "{%0,%1,%2,%3}, {%4,%5,%6,%7}, {%8,%9}, {%0,%1,%2,%3};"
        : "+f"(c[0]), "+f"(c[1]), "+f"(c[2]), "+f"(c[3])
        : "r"(a[0]), "r"(a[1]), "r"(a[2]), "r"(a[3]), "r"(b[0]), "r"(b[1]));
}

__device__ __forceinline__ void split2(float v, unsigned short& hb, unsigned short& lb){
    bf16 h = __float2bfloat16(v);
    bf16 l = __float2bfloat16(v - __bfloat162float(h));
    hb = __bfloat16_as_ushort(h);
    lb = __bfloat16_as_ushort(l);
}
__device__ __forceinline__ float warp_sum(float v){
    #pragma unroll
    for (int o = 16; o > 0; o >>= 1) v += __shfl_xor_sync(0xffffffffu, v, o);
    return v;
}

// ---------------- weight transpose + split (12 jobs, one launch) ------------
struct WJob { const float* W; bf16* hi; bf16* lo; int K; int N; };
struct WJobs { WJob j[12]; };

__global__ void wsplit_multi(WJobs jobs)
{
    __shared__ float t[32][33];
    const WJob jb = jobs.j[blockIdx.z];
    const int K = jb.K, N = jb.N;
    int nb = blockIdx.x*32, kb = blockIdx.y*32;
    if (nb >= N || kb >= K) return;
    int nx = nb + threadIdx.x;
    #pragma unroll
    for (int r = 0; r < 4; r++) {
        int k = kb + threadIdx.y + r*8;
        t[threadIdx.y + r*8][threadIdx.x] = jb.W[(size_t)k*N + nx];
    }
    __syncthreads();
    int k2 = kb + threadIdx.x;
    #pragma unroll
    for (int r = 0; r < 4; r++) {
        int n2 = nb + threadIdx.y + r*8;
        unsigned short hb, lb;
        split2(t[threadIdx.x][threadIdx.y + r*8], hb, lb);
        jb.hi[(size_t)n2*K + k2] = __ushort_as_bfloat16(hb);
        jb.lo[(size_t)n2*K + k2] = __ushort_as_bfloat16(lb);
    }
}

// ---------------- embedding + h0=0 ----------------
__global__ void embed_kernel(const int* __restrict__ x,
                             const float* __restrict__ tok,
                             const float* __restrict__ pos)
{
    int row = blockIdx.x;
    int s = row % SEQ;
    int t = x[row];
    int d = threadIdx.x * 4;
    float4 tv = *(const float4*)(tok + (size_t)t*DIM + d);
    float4 pv = *(const float4*)(pos + (size_t)s*DIM + d);
    *(float4*)&g_xemb[(size_t)row*DIM + d] = make_float4(tv.x+pv.x, tv.y+pv.y, tv.z+pv.z, tv.w+pv.w);
    *(float4*)&g_h   [(size_t)row*DIM + d] = make_float4(0.f,0.f,0.f,0.f);
}

// ---------------- layernorm, fused bf16-split output ----------------
__global__ void ln_split_kernel(const float* __restrict__ in,
                                const float* __restrict__ gamma,
                                const float* __restrict__ beta,
                                bf16* __restrict__ oh, bf16* __restrict__ ol)
{
    int row = blockIdx.x;
    int tid = threadIdx.x;   // 128
    int d = tid * 4;
    float4 v = *(const float4*)(in + (size_t)row*DIM + d);
    float s  = v.x + v.y + v.z + v.w;
    float sq = v.x*v.x + v.y*v.y + v.z*v.z + v.w*v.w;
    s = warp_sum(s); sq = warp_sum(sq);
    __shared__ float red[8]; __shared__ float mb[2];
    int w = tid >> 5, lane = tid & 31;
    if (lane == 0) { red[w] = s; red[4+w] = sq; }
    __syncthreads();
    if (tid == 0) {
        float S = red[0]+red[1]+red[2]+red[3];
        float Q = red[4]+red[5]+red[6]+red[7];
        float mu = S * (1.f/DIM);
        mb[0] = mu;
        mb[1] = rsqrtf(Q*(1.f/DIM) - mu*mu + 1e-5f);
    }
    __syncthreads();
    float mu = mb[0], inv = mb[1];
    float4 g4 = *(const float4*)(gamma + d);
    float4 b4 = *(const float4*)(beta + d);
    float r0 = (v.x-mu)*inv*g4.x + b4.x;
    float r1 = (v.y-mu)*inv*g4.y + b4.y;
    float r2 = (v.z-mu)*inv*g4.z + b4.z;
    float r3 = (v.w-mu)*inv*g4.w + b4.w;
    unsigned short hb[4], lb[4];
    split2(r0,hb[0],lb[0]); split2(r1,hb[1],lb[1]);
    split2(r2,hb[2],lb[2]); split2(r3,hb[3],lb[3]);
    uint2 hp, lp;
    hp.x = hb[0] | ((uint32_t)hb[1] << 16); hp.y = hb[2] | ((uint32_t)hb[3] << 16);
    lp.x = lb[0] | ((uint32_t)lb[1] << 16); lp.y = lb[2] | ((uint32_t)lb[3] << 16);
    *(uint2*)&oh[(size_t)row*DIM + d] = hp;
    *(uint2*)&ol[(size_t)row*DIM + d] = lp;
}

// ---------------- mma.sync GEMM, 64x64 tile, 256 thr (8 warps x 32x16) ------
struct GemmSet {
    const bf16* wh; const bf16* wl;
    const float* bias;
    float* out;
    bf16* oh; bf16* ol;
};
struct GemmArgs { GemmSet s[3]; };

#define KS      40
#define TILE_E  (64*KS)
#define TILE_B  (TILE_E*2)         // 5120 bytes
#define STAGE_B (4*TILE_B)         // Ah, Al, Bh, Bl = 20480
#define NSTAGE  3
#define GEMM_SMEM (NSTAGE*STAGE_B) // 61440

template<int EPI>
__global__ void __launch_bounds__(256)
mma_gemm(const bf16* __restrict__ a_hi, const bf16* __restrict__ a_lo,
         GemmArgs args, int M, int N, int K)
{
    extern __shared__ char smem[];
    const GemmSet gs = args.s[blockIdx.z];
    const int m0 = blockIdx.y * 64;
    const int n0 = blockIdx.x * 64;
    const int tid = threadIdx.x;
    const uint32_t sbase = smem_u32(smem);

    // loader: thread -> row tid>>2 (0..63), 16B chunk (tid&3)*8 elements
    const int lrow = tid >> 2;
    const int lke  = (tid & 3) * 8;
    const bf16* gAh = a_hi  + (size_t)(m0 + lrow)*K + lke;
    const bf16* gAl = a_lo  + (size_t)(m0 + lrow)*K + lke;
    const bf16* gBh = gs.wh + (size_t)(n0 + lrow)*K + lke;
    const bf16* gBl = gs.wl + (size_t)(n0 + lrow)*K + lke;
    const uint32_t sA = sbase + (uint32_t)(lrow*KS + lke)*2;

    auto load_stage = [&](int st, int kt){
        uint32_t b = sA + st*STAGE_B;
        CP16(b,              gAh + kt);
        CP16(b + TILE_B,     gAl + kt);
        CP16(b + 2*TILE_B,   gBh + kt);
        CP16(b + 3*TILE_B,   gBl + kt);
        CP_COMMIT();
    };

    // 8 warps: 2 (m) x 4 (n) grid of 32x16 warp tiles
    const int w  = tid >> 5, l = tid & 31;
    const int wr = (w & 1) * 32;
    const int wc = (w >> 1) * 16;

    const uint32_t aoff = (uint32_t)(((wr + (l & 15))*KS + (l >> 4)*8) * 2);
    const uint32_t boff = (uint32_t)(((wc + (l >> 4)*8 + (l & 7))*KS + ((l >> 3) & 1)*8) * 2);

    float c[2][2][4];
    #pragma unroll
    for (int i = 0; i < 2; i++)
        #pragma unroll
        for (int j = 0; j < 2; j++)
            #pragma unroll
            for (int r = 0; r < 4; r++) c[i][j][r] = 0.f;

    const int KT = K / 32;
    load_stage(0, 0);
    load_stage(1, 32);
    int s_cur = 0, s_load = 2;
    for (int kt = 0; kt < KT; kt++) {
        CP_WAIT1();
        __syncthreads();
        if (kt + 2 < KT) {
            load_stage(s_load, (kt + 2) * 32);
            s_load = (s_load == NSTAGE-1) ? 0 : s_load + 1;
        } else {
            CP_COMMIT();
        }

        const uint32_t stb = sbase + s_cur*STAGE_B;
        s_cur = (s_cur == NSTAGE-1) ? 0 : s_cur + 1;

        #pragma unroll
        for (int ks = 0; ks < 2; ks++) {
            const uint32_t kb = stb + ks*32;
            uint32_t ah[2][4], al[2][4], bb_h[4], bb_l[4];
            LDMX4(ah[0], kb + aoff);
            LDMX4(ah[1], kb + aoff + 16*KS*2);
            LDMX4(al[0], kb + TILE_B + aoff);
            LDMX4(al[1], kb + TILE_B + aoff + 16*KS*2);
            LDMX4(bb_h,  kb + 2*TILE_B + boff);
            LDMX4(bb_l,  kb + 3*TILE_B + boff);

            uint32_t bh[2][2] = {{bb_h[0],bb_h[1]},{bb_h[2],bb_h[3]}};
            uint32_t bl[2][2] = {{bb_l[0],bb_l[1]},{bb_l[2],bb_l[3]}};
            #pragma unroll
            for (int i = 0; i < 2; i++)
                #pragma unroll
                for (int j = 0; j < 2; j++) {
                    mma16816(c[i][j], ah[i], bh[j]);
                    mma16816(c[i][j], ah[i], bl[j]);
                    mma16816(c[i][j], al[i], bh[j]);
                }
        }
        __syncthreads();
    }

    const int fr = l >> 2;
    const int fc = (l & 3) * 2;
    #pragma unroll
    for (int i = 0; i < 2; i++) {
        #pragma unroll
        for (int j = 0; j < 2; j++) {
            const int cc = n0 + wc + j*8 + fc;
            float2 bv = *(const float2*)(gs.bias + cc);
            #pragma unroll
            for (int hh = 0; hh < 2; hh++) {
                const int row = m0 + wr + i*16 + fr + hh*8;
                float v0 = c[i][j][hh*2 + 0] + bv.x;
                float v1 = c[i][j][hh*2 + 1] + bv.y;
                if (EPI == 0) {
                    *(float2*)(gs.out + (size_t)row*N + cc) = make_float2(v0, v1);
                } else if (EPI == 1) {
                    float2* cp = (float2*)(gs.out + (size_t)row*N + cc);
                    float2 o = *cp;
                    o.x += v0; o.y += v1;
                    *cp = o;
                } else if (EPI == 2) {
                    unsigned short h0, l0, h1, l1;
                    split2(fmaxf(v0, 0.f), h0, l0);
                    split2(fmaxf(v1, 0.f), h1, l1);
                    *(uint32_t*)(gs.oh + (size_t)row*N + cc) = (uint32_t)h0 | ((uint32_t)h1 << 16);
                    *(uint32_t*)(gs.ol + (size_t)row*N + cc) = (uint32_t)l0 | ((uint32_t)l1 << 16);
                } else {
                    float2* cp = (float2*)(gs.out + (size_t)row*N + cc);
                    float2 h2 = *cp;
                    float2 xe = *(const float2*)&g_xemb[(size_t)row*DIM + cc];
                    h2.x = h2.x + 0.5f*(tanhf(h2.x + v0 + xe.x) - h2.x);
                    h2.y = h2.y + 0.5f*(tanhf(h2.y + v1 + xe.y) - h2.y);
                    *cp = h2;
                }
            }
        }
    }
}

// ---------------- attention: CTA = (qblock64, head, batch), 256 thr ---------
#define QB 64
#define QV_PAD 68
#define KT_PAD 132
#define SMEM_ATTN ((QB*QV_PAD + HDIM*KT_PAD + SEQ*QV_PAD + QB*KT_PAD) * (int)sizeof(float))

__global__ void __launch_bounds__(256)
attn_kernel()
{
    extern __shared__ float sm[];
    float* Qs = sm;                      // [64][68]
    float* Kt = Qs + QB*QV_PAD;          // [64][132]
    float* Vs = Kt + HDIM*KT_PAD;        // [128][68]
    float* Ps = Vs + SEQ*QV_PAD;         // [64][132]

    const int qb   = blockIdx.x;
    const int head = blockIdx.y;
    const int b    = blockIdx.z;
    const int tid  = threadIdx.x;

    const float* qg = g_q + (size_t)(b*SEQ + qb*QB)*DIM + head*HDIM;
    const float* kg = g_k + (size_t)(b*SEQ)*DIM + head*HDIM;
    const float* vg = g_v + (size_t)(b*SEQ)*DIM + head*HDIM;

    #pragma unroll
    for (int it = 0; it < 4; it++) {
        int idx = it*256 + tid;
        int s = idx >> 4, d4 = (idx & 15)*4;
        *(float4*)&Qs[s*QV_PAD + d4] = *(const float4*)(qg + (size_t)s*DIM + d4);
    }
    #pragma unroll
    for (int it = 0; it < 8; it++) {
        int idx = it*256 + tid;
        int s = idx >> 4, d4 = (idx & 15)*4;
        *(float4*)&Vs[s*QV_PAD + d4] = *(const float4*)(vg + (size_t)s*DIM + d4);
        float4 kv = *(const float4*)(kg + (size_t)s*DIM + d4);
        Kt[(d4+0)*KT_PAD + s] = kv.x;
        Kt[(d4+1)*KT_PAD + s] = kv.y;
        Kt[(d4+2)*KT_PAD + s] = kv.z;
        Kt[(d4+3)*KT_PAD + s] = kv.w;
    }
    __syncthreads();

    {
        const int i0 = (tid >> 4)*4;
        const int j0 = (tid & 15)*8;
        float acc[4][8];
        #pragma unroll
        for (int i=0;i<4;i++)
            #pragma unroll
            for (int j=0;j<8;j++) acc[i][j] = 0.f;
        for (int d = 0; d < HDIM; d++) {
            float q0 = Qs[(i0+0)*QV_PAD + d];
            float q1 = Qs[(i0+1)*QV_PAD + d];
            float q2 = Qs[(i0+2)*QV_PAD + d];
            float q3 = Qs[(i0+3)*QV_PAD + d];
            float4 k0 = *(float4*)&Kt[d*KT_PAD + j0];
            float4 k1 = *(float4*)&Kt[d*KT_PAD + j0 + 4];
            float kk[8] = {k0.x,k0.y,k0.z,k0.w,k1.x,k1.y,k1.z,k1.w};
            #pragma unroll
            for (int j=0;j<8;j++) {
                acc[0][j] = fmaf(q0, kk[j], acc[0][j]);
                acc[1][j] = fmaf(q1, kk[j], acc[1][j]);
                acc[2][j] = fmaf(q2, kk[j], acc[2][j]);
                acc[3][j] = fmaf(q3, kk[j], acc[3][j]);
            }
        }
        const float sc = 0.125f;
        #pragma unroll
        for (int i=0;i<4;i++) {
            *(float4*)&Ps[(i0+i)*KT_PAD + j0] =
                make_float4(acc[i][0]*sc, acc[i][1]*sc, acc[i][2]*sc, acc[i][3]*sc);
            *(float4*)&Ps[(i0+i)*KT_PAD + j0 + 4] =
                make_float4(acc[i][4]*sc, acc[i][5]*sc, acc[i][6]*sc, acc[i][7]*sc);
        }
    }
    __syncthreads();

    {
        const int w = tid >> 5, lane = tid & 31;
        #pragma unroll
        for (int rr = 0; rr < 8; rr++) {
            float* pr = &Ps[(w*8 + rr)*KT_PAD];
            float mx = -1e30f;
            #pragma unroll
            for (int u = 0; u < 4; u++) mx = fmaxf(mx, pr[lane + 32*u]);
            #pragma unroll
            for (int o = 16; o > 0; o >>= 1) mx = fmaxf(mx, __shfl_xor_sync(0xffffffffu, mx, o));
            float sum = 0.f;
            #pragma unroll
            for (int u = 0; u < 4; u++) {
                float e = __expf(pr[lane + 32*u] - mx);
                pr[lane + 32*u] = e;
                sum += e;
            }
            sum = warp_sum(sum);
            float inv = 1.f / sum;
            #pragma unroll
            for (int u = 0; u < 4; u++) pr[lane + 32*u] *= inv;
        }
    }
    __syncthreads();

    {
        const int r0 = (tid >> 4)*4;
        const int c0 = (tid & 15)*4;
        float oa[4][4];
        #pragma unroll
        for (int i=0;i<4;i++)
            #pragma unroll
            for (int j=0;j<4;j++) oa[i][j] = 0.f;
        const float* pr0 = &Ps[(r0+0)*KT_PAD];
        const float* pr1 = &Ps[(r0+1)*KT_PAD];
        const float* pr2 = &Ps[(r0+2)*KT_PAD];
        const float* pr3 = &Ps[(r0+3)*KT_PAD];
        for (int kk = 0; kk < SEQ; kk++) {
            float4 vv = *(float4*)&Vs[kk*QV_PAD + c0];
            float p0 = pr0[kk], p1 = pr1[kk], p2 = pr2[kk], p3 = pr3[kk];
            oa[0][0]=fmaf(p0,vv.x,oa[0][0]); oa[0][1]=fmaf(p0,vv.y,oa[0][1]);
            oa[0][2]=fmaf(p0,vv.z,oa[0][2]); oa[0][3]=fmaf(p0,vv.w,oa[0][3]);
            oa[1][0]=fmaf(p1,vv.x,oa[1][0]); oa[1][1]=fmaf(p1,vv.y,oa[1][1]);
            oa[1][2]=fmaf(p1,vv.z,oa[1][2]); oa[1][3]=fmaf(p1,vv.w,oa[1][3]);
            oa[2][0]=fmaf(p2,vv.x,oa[2][0]); oa[2][1]=fmaf(p2,vv.y,oa[2][1]);
            oa[2][2]=fmaf(p2,vv.z,oa[2][2]); oa[2][3]=fmaf(p2,vv.w,oa[2][3]);
            oa[3][0]=fmaf(p3,vv.x,oa[3][0]); oa[3][1]=fmaf(p3,vv.y,oa[3][1]);
            oa[3][2]=fmaf(p3,vv.z,oa[3][2]); oa[3][3]=fmaf(p3,vv.w,oa[3][3]);
        }
        #pragma unroll
        for (int i = 0; i < 4; i++) {
            bf16* ohg = g_o_hi + (size_t)(b*SEQ + qb*QB + r0 + i)*DIM + head*HDIM + c0;
            bf16* olg = g_o_lo + (size_t)(b*SEQ + qb*QB + r0 + i)*DIM + head*HDIM + c0;
            unsigned short hb[4], lb[4];
            #pragma unroll
            for (int j = 0; j < 4; j++) split2(oa[i][j], hb[j], lb[j]);
            uint2 hp, lp;
            hp.x = hb[0]|((uint32_t)hb[1]<<16); hp.y = hb[2]|((uint32_t)hb[3]<<16);
            lp.x = lb[0]|((uint32_t)lb[1]<<16); lp.y = lb[2]|((uint32_t)lb[3]<<16);
            *(uint2*)ohg = hp;
            *(uint2*)olg = lp;
        }
    }
}

// ---------------- mean + head ----------------
__global__ void mean_kernel()
{
    int idx = blockIdx.x*128 + threadIdx.x;
    int b = idx / DIM, d = idx % DIM;
    const float* p = g_h + (size_t)b*SEQ*DIM + d;
    float s = 0.f;
    #pragma unroll 8
    for (int ss = 0; ss < SEQ; ss++) s += p[(size_t)ss*DIM];
    g_hmean[idx] = s * (1.f/SEQ);
}

__global__ void head_kernel(const float* __restrict__ hw,
                            const float* __restrict__ hb,
                            float* __restrict__ out)
{
    int idx = blockIdx.x*128 + threadIdx.x;
    if (idx >= BATCH*NOUT) return;
    int b = idx / NOUT, o = idx % NOUT;
    const float* hm = g_hmean + b*DIM;
    float acc = hb[o];
    #pragma unroll 8
    for (int d = 0; d < DIM; d++) acc = fmaf(hm[d], hw[(size_t)d*NOUT + o], acc);
    out[idx] = acc;
}

// ---------------- host ----------------
template<int EPI>
static void launch_mma(const bf16* ah, const bf16* al, const GemmArgs& ga,
                       int M, int N, int K, int nz)
{
    dim3 grid(N/64, M/64, nz), block(256);
    mma_gemm<EPI><<<grid, block, GEMM_SMEM>>>(ah, al, ga, M, N, K);
}

extern "C" void kernel_launch(void* const* d_in, const int* in_sizes, int n_in,
                              void* d_out, int out_size)
{
    const int*   x   = (const int*)  d_in[0];
    const float* tok = (const float*)d_in[2];
    const float* pos = (const float*)d_in[3];
    const float* Wq  = (const float*)d_in[4];
    const float* bq  = (const float*)d_in[5];
    const float* Wk  = (const float*)d_in[6];
    const float* bk  = (const float*)d_in[7];
    const float* Wv  = (const float*)d_in[8];
    const float* bv  = (const float*)d_in[9];
    const float* Wo  = (const float*)d_in[10];
    const float* bo  = (const float*)d_in[11];
    const float* W1  = (const float*)d_in[12];
    const float* b1  = (const float*)d_in[13];
    const float* W2  = (const float*)d_in[14];
    const float* b2  = (const float*)d_in[15];
    const float* l1g = (const float*)d_in[16];
    const float* l1b = (const float*)d_in[17];
    const float* l2g = (const float*)d_in[18];
    const float* l2b = (const float*)d_in[19];
    const float* hw  = (const float*)d_in[20];
    const float* hb  = (const float*)d_in[21];
    float* out = (float*)d_out;

    void *p_h, *p_q, *p_k, *p_v, *p_hnh, *p_hnl, *p_oh, *p_ol, *p_mh, *p_ml, *p_wh, *p_wl;
    cudaGetSymbolAddress(&p_h,  g_h);
    cudaGetSymbolAddress(&p_q,  g_q);
    cudaGetSymbolAddress(&p_k,  g_k);
    cudaGetSymbolAddress(&p_v,  g_v);
    cudaGetSymbolAddress(&p_hnh, g_hn_hi);
    cudaGetSymbolAddress(&p_hnl, g_hn_lo);
    cudaGetSymbolAddress(&p_oh, g_o_hi);
    cudaGetSymbolAddress(&p_ol, g_o_lo);
    cudaGetSymbolAddress(&p_mh, g_mid_hi);
    cudaGetSymbolAddress(&p_ml, g_mid_lo);
    cudaGetSymbolAddress(&p_wh, g_wh);
    cudaGetSymbolAddress(&p_wl, g_wl);
    float* hB = (float*)p_h;
    bf16 *hnh = (bf16*)p_hnh, *hnl = (bf16*)p_hnl;
    bf16 *ohB = (bf16*)p_oh,  *olB = (bf16*)p_ol;
    bf16 *mhB = (bf16*)p_mh,  *mlB = (bf16*)p_ml;
    bf16 *whB = (bf16*)p_wh,  *wlB = (bf16*)p_wl;

    static bool attr_done = false;
    if (!attr_done) {
        cudaFuncSetAttribute(attn_kernel,  cudaFuncAttributeMaxDynamicSharedMemorySize, SMEM_ATTN);
        cudaFuncSetAttribute(mma_gemm<0>, cudaFuncAttributeMaxDynamicSharedMemorySize, GEMM_SMEM);
        cudaFuncSetAttribute(mma_gemm<1>, cudaFuncAttributeMaxDynamicSharedMemorySize, GEMM_SMEM);
        cudaFuncSetAttribute(mma_gemm<2>, cudaFuncAttributeMaxDynamicSharedMemorySize, GEMM_SMEM);
        cudaFuncSetAttribute(mma_gemm<3>, cudaFuncAttributeMaxDynamicSharedMemorySize, GEMM_SMEM);
        attr_done = true;
    }

    // weight transpose + split: one launch, 12 jobs
    {
        bf16* l0h = whB;          bf16* l0l = wlB;
        bf16* l1h = whB + WLAYER; bf16* l1l = wlB + WLAYER;
        WJobs wj{};
        wj.j[0]  = {Wq,           l0h + WOFF_Q, l0l + WOFF_Q, DIM, DIM};
        wj.j[1]  = {Wk,           l0h + WOFF_K, l0l + WOFF_K, DIM, DIM};
        wj.j[2]  = {Wv,           l0h + WOFF_V, l0l + WOFF_V, DIM, DIM};
        wj.j[3]  = {Wo,           l0h + WOFF_O, l0l + WOFF_O, DIM, DIM};
        wj.j[4]  = {W1,           l0h + WOFF_1, l0l + WOFF_1, DIM, DFF};
        wj.j[5]  = {W2,           l0h + WOFF_2, l0l + WOFF_2, DFF, DIM};
        wj.j[6]  = {Wq + DIM*DIM, l1h + WOFF_Q, l1l + WOFF_Q, DIM, DIM};
        wj.j[7]  = {Wk + DIM*DIM, l1h + WOFF_K, l1l + WOFF_K, DIM, DIM};
        wj.j[8]  = {Wv + DIM*DIM, l1h + WOFF_V, l1l + WOFF_V, DIM, DIM};
        wj.j[9]  = {Wo + DIM*DIM, l1h + WOFF_O, l1l + WOFF_O, DIM, DIM};
        wj.j[10] = {W1 + DIM*DFF, l1h + WOFF_1, l1l + WOFF_1, DIM, DFF};
        wj.j[11] = {W2 + DIM*DFF, l1h + WOFF_2, l1l + WOFF_2, DFF, DIM};
        wsplit_multi<<<dim3(32, 32, 12), dim3(32, 8)>>>(wj);
    }

    embed_kernel<<<NROWS, 128>>>(x, tok, pos);

    float* qkv[3] = {(float*)p_q, (float*)p_k, (float*)p_v};
    for (int st = 0; st < NSTEPS; st++) {
        for (int l = 0; l < NLAYER; l++) {
            const size_t vd = (size_t)l*DIM, vf = (size_t)l*DFF;
            bf16* lh = whB + (size_t)l*WLAYER;
            bf16* ll = wlB + (size_t)l*WLAYER;

            ln_split_kernel<<<NROWS, 128>>>(hB, l1g + vd, l1b + vd, hnh, hnl);

            GemmArgs ga{};
            ga.s[0] = {lh + WOFF_Q, ll + WOFF_Q, bq + vd, qkv[0], nullptr, nullptr};
            ga.s[1] = {lh + WOFF_K, ll + WOFF_K, bk + vd, qkv[1], nullptr, nullptr};
            ga.s[2] = {lh + WOFF_V, ll + WOFF_V, bv + vd, qkv[2], nullptr, nullptr};
            launch_mma<0>(hnh, hnl, ga, NROWS, DIM, DIM, 3);

            attn_kernel<<<dim3(SEQ/QB, NHEAD, BATCH), 256, SMEM_ATTN>>>();

            GemmArgs go{};
            go.s[0] = {lh + WOFF_O, ll + WOFF_O, bo + vd, hB, nullptr, nullptr};
            launch_mma<1>(ohB, olB, go, NROWS, DIM, DIM, 1);

            ln_split_kernel<<<NROWS, 128>>>(hB, l2g + vd, l2b + vd, hnh, hnl);

            GemmArgs g1{};
            g1.s[0] = {lh + WOFF_1, ll + WOFF_1, b1 + vf, nullptr, mhB, mlB};
            launch_mma<2>(hnh, hnl, g1, NROWS, DFF, DIM, 1);

            GemmArgs g2{};
            g2.s[0] = {lh + WOFF_2, ll + WOFF_2, b2 + vd, hB, nullptr, nullptr};
            launch_mma<3>(mhB, mlB, g2, NROWS, DIM, DFF, 1);
        }
    }

    mean_kernel<<<BATCH*DIM/128, 128>>>();
    head_kernel<<<(BATCH*NOUT + 127)/128, 128>>>(hw, hb, out);
}

// round 15
// speedup vs baseline: 1.1380x; 1.0131x over previous
#include <cuda_runtime.h>
#include <cuda_bf16.h>
#include <cstdint>
#include <math.h>

#define BATCH 8
#define SEQ 128
#define DIM 512
#define NHEAD 8
#define HDIM 64
#define NLAYER 2
#define NSTEPS 20
#define DFF 1024
#define NOUT 1000
#define NROWS (BATCH*SEQ)

typedef __nv_bfloat16 bf16;

// ---------------- scratch ----------------
__device__ float g_xemb[NROWS*DIM];
__device__ float g_h   [NROWS*DIM];
__device__ float g_q   [NROWS*DIM];
__device__ float g_k   [NROWS*DIM];
__device__ float g_v   [NROWS*DIM];
__device__ float g_hmean[BATCH*DIM];
__device__ __align__(16) bf16 g_hn_hi [NROWS*DIM];
__device__ __align__(16) bf16 g_hn_lo [NROWS*DIM];
__device__ __align__(16) bf16 g_o_hi  [NROWS*DIM];
__device__ __align__(16) bf16 g_o_lo  [NROWS*DIM];
__device__ __align__(16) bf16 g_mid_hi[NROWS*DFF];
__device__ __align__(16) bf16 g_mid_lo[NROWS*DFF];

#define WOFF_Q 0
#define WOFF_K (DIM*DIM)
#define WOFF_V (2*DIM*DIM)
#define WOFF_O (3*DIM*DIM)
#define WOFF_1 (4*DIM*DIM)
#define WOFF_2 (4*DIM*DIM + DFF*DIM)
#define WLAYER (4*DIM*DIM + 2*DFF*DIM)
__device__ __align__(16) bf16 g_wh[NLAYER*WLAYER];
__device__ __align__(16) bf16 g_wl[NLAYER*WLAYER];

// ---------------- helpers ----------------
__device__ __forceinline__ uint32_t smem_u32(const void* p){
    uint32_t a;
    asm("{ .reg .u64 t; cvta.to.shared.u64 t, %1; cvt.u32.u64 %0, t; }" : "=r"(a) : "l"(p));
    return a;
}
#define CP16(sa, gp) \
    asm volatile("cp.async.cg.shared.global [%0], [%1], 16;" :: "r"(sa), "l"(gp))
#define CP_COMMIT() asm volatile("cp.async.commit_group;" ::: "memory")
#define CP_WAIT1()  asm volatile("cp.async.wait_group 1;" ::: "memory")

#define LDMX4(r, addr) \
    asm volatile("ldmatrix.sync.aligned.m8n8.x4.shared.b16 {%0,%1,%2,%3}, [%4];" \
        : "=r"((r)[0]), "=r"((r)[1]), "=r"((r)[2]), "=r"((r)[3]) : "r"(addr))

__device__ __forceinline__ void mma16816(float* c, const uint32_t* a, const uint32_t* b){
    asm volatile("mma.sync.aligned.m16n8k16.row.col.f32.bf16.bf16.f32 "
        "{%0,%1,%2,%3}, {%4,%5,%6,%7}, {%8,%9}, {%0,%1,%2,%3};"
        : "+f"(c[0]), "+f"(c[1]), "+f"(c[2]), "+f"(c[3])
        : "r"(a[0]), "r"(a[1]), "r"(a[2]), "r"(a[3]), "r"(b[0]), "r"(b[1]));
}

__device__ __forceinline__ void split2(float v, unsigned short& hb, unsigned short& lb){
    bf16 h = __float2bfloat16(v);
    bf16 l = __float2bfloat16(v - __bfloat162float(h));
    hb = __bfloat16_as_ushort(h);
    lb = __bfloat16_as_ushort(l);
}
__device__ __forceinline__ float warp_sum(float v){
    #pragma unroll
    for (int o = 16; o > 0; o >>= 1) v += __shfl_xor_sync(0xffffffffu, v, o);
    return v;
}

// ---------------- weight transpose + split (12 jobs, one launch) ------------
struct WJob { const float* W; bf16* hi; bf16* lo; int K; int N; };
struct WJobs { WJob j[12]; };

__global__ void wsplit_multi(WJobs jobs)
{
    __shared__ float t[32][33];
    const WJob jb = jobs.j[blockIdx.z];
    const int K = jb.K, N = jb.N;
    int nb = blockIdx.x*32, kb = blockIdx.y*32;
    if (nb >= N || kb >= K) return;
    int nx = nb + threadIdx.x;
    #pragma unroll
    for (int r = 0; r < 4; r++) {
        int k = kb + threadIdx.y + r*8;
        t[threadIdx.y + r*8][threadIdx.x] = jb.W[(size_t)k*N + nx];
    }
    __syncthreads();
    int k2 = kb + threadIdx.x;
    #pragma unroll
    for (int r = 0; r < 4; r++) {
        int n2 = nb + threadIdx.y + r*8;
        unsigned short hb, lb;
        split2(t[threadIdx.x][threadIdx.y + r*8], hb, lb);
        jb.hi[(size_t)n2*K + k2] = __ushort_as_bfloat16(hb);
        jb.lo[(size_t)n2*K + k2] = __ushort_as_bfloat16(lb);
    }
}

// ---------------- embedding + h0=0 ----------------
__global__ void embed_kernel(const int* __restrict__ x,
                             const float* __restrict__ tok,
                             const float* __restrict__ pos)
{
    int row = blockIdx.x;
    int s = row % SEQ;
    int t = x[row];
    int d = threadIdx.x * 4;
    float4 tv = *(const float4*)(tok + (size_t)t*DIM + d);
    float4 pv = *(const float4*)(pos + (size_t)s*DIM + d);
    *(float4*)&g_xemb[(size_t)row*DIM + d] = make_float4(tv.x+pv.x, tv.y+pv.y, tv.z+pv.z, tv.w+pv.w);
    *(float4*)&g_h   [(size_t)row*DIM + d] = make_float4(0.f,0.f,0.f,0.f);
}

// ---------------- layernorm, fused bf16-split output ----------------
__global__ void ln_split_kernel(const float* __restrict__ in,
                                const float* __restrict__ gamma,
                                const float* __restrict__ beta,
                                bf16* __restrict__ oh, bf16* __restrict__ ol)
{
    int row = blockIdx.x;
    int tid = threadIdx.x;   // 128
    int d = tid * 4;
    float4 v = *(const float4*)(in + (size_t)row*DIM + d);
    float s  = v.x + v.y + v.z + v.w;
    float sq = v.x*v.x + v.y*v.y + v.z*v.z + v.w*v.w;
    s = warp_sum(s); sq = warp_sum(sq);
    __shared__ float red[8]; __shared__ float mb[2];
    int w = tid >> 5, lane = tid & 31;
    if (lane == 0) { red[w] = s; red[4+w] = sq; }
    __syncthreads();
    if (tid == 0) {
        float S = red[0]+red[1]+red[2]+red[3];
        float Q = red[4]+red[5]+red[6]+red[7];
        float mu = S * (1.f/DIM);
        mb[0] = mu;
        mb[1] = rsqrtf(Q*(1.f/DIM) - mu*mu + 1e-5f);
    }
    __syncthreads();
    float mu = mb[0], inv = mb[1];
    float4 g4 = *(const float4*)(gamma + d);
    float4 b4 = *(const float4*)(beta + d);
    float r0 = (v.x-mu)*inv*g4.x + b4.x;
    float r1 = (v.y-mu)*inv*g4.y + b4.y;
    float r2 = (v.z-mu)*inv*g4.z + b4.z;
    float r3 = (v.w-mu)*inv*g4.w + b4.w;
    unsigned short hb[4], lb[4];
    split2(r0,hb[0],lb[0]); split2(r1,hb[1],lb[1]);
    split2(r2,hb[2],lb[2]); split2(r3,hb[3],lb[3]);
    uint2 hp, lp;
    hp.x = hb[0] | ((uint32_t)hb[1] << 16); hp.y = hb[2] | ((uint32_t)hb[3] << 16);
    lp.x = lb[0] | ((uint32_t)lb[1] << 16); lp.y = lb[2] | ((uint32_t)lb[3] << 16);
    *(uint2*)&oh[(size_t)row*DIM + d] = hp;
    *(uint2*)&ol[(size_t)row*DIM + d] = lp;
}

// ---------------- mma.sync GEMM, 64x64 tile, 256 thr, split accumulators ----
struct GemmSet {
    const bf16* wh; const bf16* wl;
    const float* bias;
    float* out;
    bf16* oh; bf16* ol;
};
struct GemmArgs { GemmSet s[3]; };

#define KS      40
#define TILE_E  (64*KS)
#define TILE_B  (TILE_E*2)         // 5120 bytes
#define STAGE_B (4*TILE_B)         // Ah, Al, Bh, Bl = 20480
#define NSTAGE  3
#define GEMM_SMEM (NSTAGE*STAGE_B) // 61440

template<int EPI>
__global__ void __launch_bounds__(256)
mma_gemm(const bf16* __restrict__ a_hi, const bf16* __restrict__ a_lo,
         GemmArgs args, int M, int N, int K)
{
    extern __shared__ char smem[];
    const GemmSet gs = args.s[blockIdx.z];
    const int m0 = blockIdx.y * 64;
    const int n0 = blockIdx.x * 64;
    const int tid = threadIdx.x;
    const uint32_t sbase = smem_u32(smem);

    // loader: thread -> row tid>>2 (0..63), 16B chunk (tid&3)*8 elements
    const int lrow = tid >> 2;
    const int lke  = (tid & 3) * 8;
    const bf16* gAh = a_hi  + (size_t)(m0 + lrow)*K + lke;
    const bf16* gAl = a_lo  + (size_t)(m0 + lrow)*K + lke;
    const bf16* gBh = gs.wh + (size_t)(n0 + lrow)*K + lke;
    const bf16* gBl = gs.wl + (size_t)(n0 + lrow)*K + lke;
    const uint32_t sA = sbase + (uint32_t)(lrow*KS + lke)*2;

    auto load_stage = [&](int st, int kt){
        uint32_t b = sA + st*STAGE_B;
        CP16(b,              gAh + kt);
        CP16(b + TILE_B,     gAl + kt);
        CP16(b + 2*TILE_B,   gBh + kt);
        CP16(b + 3*TILE_B,   gBl + kt);
        CP_COMMIT();
    };

    // 8 warps: 2 (m) x 4 (n) grid of 32x16 warp tiles
    const int w  = tid >> 5, l = tid & 31;
    const int wr = (w & 1) * 32;
    const int wc = (w >> 1) * 16;

    const uint32_t aoff = (uint32_t)(((wr + (l & 15))*KS + (l >> 4)*8) * 2);
    const uint32_t boff = (uint32_t)(((wc + (l >> 4)*8 + (l & 7))*KS + ((l >> 3) & 1)*8) * 2);

    // split accumulators: d = hi*hi term, e = hi*lo + lo*hi correction terms
    float d[2][2][4], e[2][2][4];
    #pragma unroll
    for (int i = 0; i < 2; i++)
        #pragma unroll
        for (int j = 0; j < 2; j++)
            #pragma unroll
            for (int r = 0; r < 4; r++) { d[i][j][r] = 0.f; e[i][j][r] = 0.f; }

    const int KT = K / 32;
    load_stage(0, 0);
    load_stage(1, 32);
    int s_cur = 0, s_load = 2;
    for (int kt = 0; kt < KT; kt++) {
        CP_WAIT1();
        __syncthreads();   // single barrier per iter: orders prev-iter reads before new writes
        if (kt + 2 < KT) {
            load_stage(s_load, (kt + 2) * 32);
            s_load = (s_load == NSTAGE-1) ? 0 : s_load + 1;
        } else {
            CP_COMMIT();
        }

        const uint32_t stb = sbase + s_cur*STAGE_B;
        s_cur = (s_cur == NSTAGE-1) ? 0 : s_cur + 1;

        #pragma unroll
        for (int ks = 0; ks < 2; ks++) {
            const uint32_t kb = stb + ks*32;
            uint32_t ah[2][4], al[2][4], bb_h[4], bb_l[4];
            LDMX4(ah[0], kb + aoff);
            LDMX4(ah[1], kb + aoff + 16*KS*2);
            LDMX4(al[0], kb + TILE_B + aoff);
            LDMX4(al[1], kb + TILE_B + aoff + 16*KS*2);
            LDMX4(bb_h,  kb + 2*TILE_B + boff);
            LDMX4(bb_l,  kb + 3*TILE_B + boff);

            uint32_t bh[2][2] = {{bb_h[0],bb_h[1]},{bb_h[2],bb_h[3]}};
            uint32_t bl[2][2] = {{bb_l[0],bb_l[1]},{bb_l[2],bb_l[3]}};
            #pragma unroll
            for (int i = 0; i < 2; i++)
                #pragma unroll
                for (int j = 0; j < 2; j++) {
                    mma16816(d[i][j], ah[i], bh[j]);   // main term -> d
                    mma16816(e[i][j], ah[i], bl[j]);   // corrections -> e
                    mma16816(e[i][j], al[i], bh[j]);
                }
        }
    }
    __syncthreads();

    const int fr = l >> 2;
    const int fc = (l & 3) * 2;
    #pragma unroll
    for (int i = 0; i < 2; i++) {
        #pragma unroll
        for (int j = 0; j < 2; j++) {
            const int cc = n0 + wc + j*8 + fc;
            float2 bv = *(const float2*)(gs.bias + cc);
            #pragma unroll
            for (int hh = 0; hh < 2; hh++) {
                const int row = m0 + wr + i*16 + fr + hh*8;
                float v0 = d[i][j][hh*2 + 0] + e[i][j][hh*2 + 0] + bv.x;
                float v1 = d[i][j][hh*2 + 1] + e[i][j][hh*2 + 1] + bv.y;
                if (EPI == 0) {
                    *(float2*)(gs.out + (size_t)row*N + cc) = make_float2(v0, v1);
                } else if (EPI == 1) {
                    float2* cp = (float2*)(gs.out + (size_t)row*N + cc);
                    float2 o = *cp;
                    o.x += v0; o.y += v1;
                    *cp = o;
                } else if (EPI == 2) {
                    unsigned short h0, l0, h1, l1;
                    split2(fmaxf(v0, 0.f), h0, l0);
                    split2(fmaxf(v1, 0.f), h1, l1);
                    *(uint32_t*)(gs.oh + (size_t)row*N + cc) = (uint32_t)h0 | ((uint32_t)h1 << 16);
                    *(uint32_t*)(gs.ol + (size_t)row*N + cc) = (uint32_t)l0 | ((uint32_t)l1 << 16);
                } else {
                    float2* cp = (float2*)(gs.out + (size_t)row*N + cc);
                    float2 h2 = *cp;
                    float2 xe = *(const float2*)&g_xemb[(size_t)row*DIM + cc];
                    h2.x = h2.x + 0.5f*(tanhf(h2.x + v0 + xe.x) - h2.x);
                    h2.y = h2.y + 0.5f*(tanhf(h2.y + v1 + xe.y) - h2.y);
                    *cp = h2;
                }
            }
        }
    }
}

// ---------------- attention: CTA = (qblock64, head, batch), 256 thr ---------
#define QB 64
#define QV_PAD 68
#define KT_PAD 132
#define SMEM_ATTN ((QB*QV_PAD + HDIM*KT_PAD + SEQ*QV_PAD + QB*KT_PAD) * (int)sizeof(float))

__global__ void __launch_bounds__(256)
attn_kernel()
{
    extern __shared__ float sm[];
    float* Qs = sm;                      // [64][68]
    float* Kt = Qs + QB*QV_PAD;          // [64][132]
    float* Vs = Kt + HDIM*KT_PAD;        // [128][68]
    float* Ps = Vs + SEQ*QV_PAD;         // [64][132]

    const int qb   = blockIdx.x;
    const int head = blockIdx.y;
    const int b    = blockIdx.z;
    const int tid  = threadIdx.x;

    const float* qg = g_q + (size_t)(b*SEQ + qb*QB)*DIM + head*HDIM;
    const float* kg = g_k + (size_t)(b*SEQ)*DIM + head*HDIM;
    const float* vg = g_v + (size_t)(b*SEQ)*DIM + head*HDIM;

    #pragma unroll
    for (int it = 0; it < 4; it++) {
        int idx = it*256 + tid;
        int s = idx >> 4, d4 = (idx & 15)*4;
        *(float4*)&Qs[s*QV_PAD + d4] = *(const float4*)(qg + (size_t)s*DIM + d4);
    }
    #pragma unroll
    for (int it = 0; it < 8; it++) {
        int idx = it*256 + tid;
        int s = idx >> 4, d4 = (idx & 15)*4;
        *(float4*)&Vs[s*QV_PAD + d4] = *(const float4*)(vg + (size_t)s*DIM + d4);
        float4 kv = *(const float4*)(kg + (size_t)s*DIM + d4);
        Kt[(d4+0)*KT_PAD + s] = kv.x;
        Kt[(d4+1)*KT_PAD + s] = kv.y;
        Kt[(d4+2)*KT_PAD + s] = kv.z;
        Kt[(d4+3)*KT_PAD + s] = kv.w;
    }
    __syncthreads();

    {
        const int i0 = (tid >> 4)*4;
        const int j0 = (tid & 15)*8;
        float acc[4][8];
        #pragma unroll
        for (int i=0;i<4;i++)
            #pragma unroll
            for (int j=0;j<8;j++) acc[i][j] = 0.f;
        for (int dd = 0; dd < HDIM; dd++) {
            float q0 = Qs[(i0+0)*QV_PAD + dd];
            float q1 = Qs[(i0+1)*QV_PAD + dd];
            float q2 = Qs[(i0+2)*QV_PAD + dd];
            float q3 = Qs[(i0+3)*QV_PAD + dd];
            float4 k0 = *(float4*)&Kt[dd*KT_PAD + j0];
            float4 k1 = *(float4*)&Kt[dd*KT_PAD + j0 + 4];
            float kk[8] = {k0.x,k0.y,k0.z,k0.w,k1.x,k1.y,k1.z,k1.w};
            #pragma unroll
            for (int j=0;j<8;j++) {
                acc[0][j] = fmaf(q0, kk[j], acc[0][j]);
                acc[1][j] = fmaf(q1, kk[j], acc[1][j]);
                acc[2][j] = fmaf(q2, kk[j], acc[2][j]);
                acc[3][j] = fmaf(q3, kk[j], acc[3][j]);
            }
        }
        const float sc = 0.125f;
        #pragma unroll
        for (int i=0;i<4;i++) {
            *(float4*)&Ps[(i0+i)*KT_PAD + j0] =
                make_float4(acc[i][0]*sc, acc[i][1]*sc, acc[i][2]*sc, acc[i][3]*sc);
            *(float4*)&Ps[(i0+i)*KT_PAD + j0 + 4] =
                make_float4(acc[i][4]*sc, acc[i][5]*sc, acc[i][6]*sc, acc[i][7]*sc);
        }
    }
    __syncthreads();

    {
        const int w = tid >> 5, lane = tid & 31;
        #pragma unroll
        for (int rr = 0; rr < 8; rr++) {
            float* pr = &Ps[(w*8 + rr)*KT_PAD];
            float mx = -1e30f;
            #pragma unroll
            for (int u = 0; u < 4; u++) mx = fmaxf(mx, pr[lane + 32*u]);
            #pragma unroll
            for (int o = 16; o > 0; o >>= 1) mx = fmaxf(mx, __shfl_xor_sync(0xffffffffu, mx, o));
            float sum = 0.f;
            #pragma unroll
            for (int u = 0; u < 4; u++) {
                float ee = __expf(pr[lane + 32*u] - mx);
                pr[lane + 32*u] = ee;
                sum += ee;
            }
            sum = warp_sum(sum);
            float inv = 1.f / sum;
            #pragma unroll
            for (int u = 0; u < 4; u++) pr[lane + 32*u] *= inv;
        }
    }
    __syncthreads();

    {
        const int r0 = (tid >> 4)*4;
        const int c0 = (tid & 15)*4;
        float oa[4][4];
        #pragma unroll
        for (int i=0;i<4;i++)
            #pragma unroll
            for (int j=0;j<4;j++) oa[i][j] = 0.f;
        const float* pr0 = &Ps[(r0+0)*KT_PAD];
        const float* pr1 = &Ps[(r0+1)*KT_PAD];
        const float* pr2 = &Ps[(r0+2)*KT_PAD];
        const float* pr3 = &Ps[(r0+3)*KT_PAD];
        for (int kk = 0; kk < SEQ; kk++) {
            float4 vv = *(float4*)&Vs[kk*QV_PAD + c0];
            float p0 = pr0[kk], p1 = pr1[kk], p2 = pr2[kk], p3 = pr3[kk];
            oa[0][0]=fmaf(p0,vv.x,oa[0][0]); oa[0][1]=fmaf(p0,vv.y,oa[0][1]);
            oa[0][2]=fmaf(p0,vv.z,oa[0][2]); oa[0][3]=fmaf(p0,vv.w,oa[0][3]);
            oa[1][0]=fmaf(p1,vv.x,oa[1][0]); oa[1][1]=fmaf(p1,vv.y,oa[1][1]);
            oa[1][2]=fmaf(p1,vv.z,oa[1][2]); oa[1][3]=fmaf(p1,vv.w,oa[1][3]);
            oa[2][0]=fmaf(p2,vv.x,oa[2][0]); oa[2][1]=fmaf(p2,vv.y,oa[2][1]);
            oa[2][2]=fmaf(p2,vv.z,oa[2][2]); oa[2][3]=fmaf(p2,vv.w,oa[2][3]);
            oa[3][0]=fmaf(p3,vv.x,oa[3][0]); oa[3][1]=fmaf(p3,vv.y,oa[3][1]);
            oa[3][2]=fmaf(p3,vv.z,oa[3][2]); oa[3][3]=fmaf(p3,vv.w,oa[3][3]);
        }
        #pragma unroll
        for (int i = 0; i < 4; i++) {
            bf16* ohg = g_o_hi + (size_t)(b*SEQ + qb*QB + r0 + i)*DIM + head*HDIM + c0;
            bf16* olg = g_o_lo + (size_t)(b*SEQ + qb*QB + r0 + i)*DIM + head*HDIM + c0;
            unsigned short hb[4], lb[4];
            #pragma unroll
            for (int j = 0; j < 4; j++) split2(oa[i][j], hb[j], lb[j]);
            uint2 hp, lp;
            hp.x = hb[0]|((uint32_t)hb[1]<<16); hp.y = hb[2]|((uint32_t)hb[3]<<16);
            lp.x = lb[0]|((uint32_t)lb[1]<<16); lp.y = lb[2]|((uint32_t)lb[3]<<16);
            *(uint2*)ohg = hp;
            *(uint2*)olg = lp;
        }
    }
}

// ---------------- mean + head ----------------
__global__ void mean_kernel()
{
    int idx = blockIdx.x*128 + threadIdx.x;
    int b = idx / DIM, d = idx % DIM;
    const float* p = g_h + (size_t)b*SEQ*DIM + d;
    float s = 0.f;
    #pragma unroll 8
    for (int ss = 0; ss < SEQ; ss++) s += p[(size_t)ss*DIM];
    g_hmean[idx] = s * (1.f/SEQ);
}

__global__ void head_kernel(const float* __restrict__ hw,
                            const float* __restrict__ hb,
                            float* __restrict__ out)
{
    int idx = blockIdx.x*128 + threadIdx.x;
    if (idx >= BATCH*NOUT) return;
    int b = idx / NOUT, o = idx % NOUT;
    const float* hm = g_hmean + b*DIM;
    float acc = hb[o];
    #pragma unroll 8
    for (int d = 0; d < DIM; d++) acc = fmaf(hm[d], hw[(size_t)d*NOUT + o], acc);
    out[idx] = acc;
}

// ---------------- host ----------------
template<int EPI>
static void launch_mma(const bf16* ah, const bf16* al, const GemmArgs& ga,
                       int M, int N, int K, int nz)
{
    dim3 grid(N/64, M/64, nz), block(256);
    mma_gemm<EPI><<<grid, block, GEMM_SMEM>>>(ah, al, ga, M, N, K);
}

extern "C" void kernel_launch(void* const* d_in, const int* in_sizes, int n_in,
                              void* d_out, int out_size)
{
    const int*   x   = (const int*)  d_in[0];
    const float* tok = (const float*)d_in[2];
    const float* pos = (const float*)d_in[3];
    const float* Wq  = (const float*)d_in[4];
    const float* bq  = (const float*)d_in[5];
    const float* Wk  = (const float*)d_in[6];
    const float* bk  = (const float*)d_in[7];
    const float* Wv  = (const float*)d_in[8];
    const float* bv  = (const float*)d_in[9];
    const float* Wo  = (const float*)d_in[10];
    const float* bo  = (const float*)d_in[11];
    const float* W1  = (const float*)d_in[12];
    const float* b1  = (const float*)d_in[13];
    const float* W2  = (const float*)d_in[14];
    const float* b2  = (const float*)d_in[15];
    const float* l1g = (const float*)d_in[16];
    const float* l1b = (const float*)d_in[17];
    const float* l2g = (const float*)d_in[18];
    const float* l2b = (const float*)d_in[19];
    const float* hw  = (const float*)d_in[20];
    const float* hb  = (const float*)d_in[21];
    float* out = (float*)d_out;

    void *p_h, *p_q, *p_k, *p_v, *p_hnh, *p_hnl, *p_oh, *p_ol, *p_mh, *p_ml, *p_wh, *p_wl;
    cudaGetSymbolAddress(&p_h,  g_h);
    cudaGetSymbolAddress(&p_q,  g_q);
    cudaGetSymbolAddress(&p_k,  g_k);
    cudaGetSymbolAddress(&p_v,  g_v);
    cudaGetSymbolAddress(&p_hnh, g_hn_hi);
    cudaGetSymbolAddress(&p_hnl, g_hn_lo);
    cudaGetSymbolAddress(&p_oh, g_o_hi);
    cudaGetSymbolAddress(&p_ol, g_o_lo);
    cudaGetSymbolAddress(&p_mh, g_mid_hi);
    cudaGetSymbolAddress(&p_ml, g_mid_lo);
    cudaGetSymbolAddress(&p_wh, g_wh);
    cudaGetSymbolAddress(&p_wl, g_wl);
    float* hB = (float*)p_h;
    bf16 *hnh = (bf16*)p_hnh, *hnl = (bf16*)p_hnl;
    bf16 *ohB = (bf16*)p_oh,  *olB = (bf16*)p_ol;
    bf16 *mhB = (bf16*)p_mh,  *mlB = (bf16*)p_ml;
    bf16 *whB = (bf16*)p_wh,  *wlB = (bf16*)p_wl;

    static bool attr_done = false;
    if (!attr_done) {
        cudaFuncSetAttribute(attn_kernel,  cudaFuncAttributeMaxDynamicSharedMemorySize, SMEM_ATTN);
        cudaFuncSetAttribute(mma_gemm<0>, cudaFuncAttributeMaxDynamicSharedMemorySize, GEMM_SMEM);
        cudaFuncSetAttribute(mma_gemm<1>, cudaFuncAttributeMaxDynamicSharedMemorySize, GEMM_SMEM);
        cudaFuncSetAttribute(mma_gemm<2>, cudaFuncAttributeMaxDynamicSharedMemorySize, GEMM_SMEM);
        cudaFuncSetAttribute(mma_gemm<3>, cudaFuncAttributeMaxDynamicSharedMemorySize, GEMM_SMEM);
        attr_done = true;
    }

    // weight transpose + split: one launch, 12 jobs
    {
        bf16* l0h = whB;          bf16* l0l = wlB;
        bf16* l1h = whB + WLAYER; bf16* l1l = wlB + WLAYER;
        WJobs wj{};
        wj.j[0]  = {Wq,           l0h + WOFF_Q, l0l + WOFF_Q, DIM, DIM};
        wj.j[1]  = {Wk,           l0h + WOFF_K, l0l + WOFF_K, DIM, DIM};
        wj.j[2]  = {Wv,           l0h + WOFF_V, l0l + WOFF_V, DIM, DIM};
        wj.j[3]  = {Wo,           l0h + WOFF_O, l0l + WOFF_O, DIM, DIM};
        wj.j[4]  = {W1,           l0h + WOFF_1, l0l + WOFF_1, DIM, DFF};
        wj.j[5]  = {W2,           l0h + WOFF_2, l0l + WOFF_2, DFF, DIM};
        wj.j[6]  = {Wq + DIM*DIM, l1h + WOFF_Q, l1l + WOFF_Q, DIM, DIM};
        wj.j[7]  = {Wk + DIM*DIM, l1h + WOFF_K, l1l + WOFF_K, DIM, DIM};
        wj.j[8]  = {Wv + DIM*DIM, l1h + WOFF_V, l1l + WOFF_V, DIM, DIM};
        wj.j[9]  = {Wo + DIM*DIM, l1h + WOFF_O, l1l + WOFF_O, DIM, DIM};
        wj.j[10] = {W1 + DIM*DFF, l1h + WOFF_1, l1l + WOFF_1, DIM, DFF};
        wj.j[11] = {W2 + DIM*DFF, l1h + WOFF_2, l1l + WOFF_2, DFF, DIM};
        wsplit_multi<<<dim3(32, 32, 12), dim3(32, 8)>>>(wj);
    }

    embed_kernel<<<NROWS, 128>>>(x, tok, pos);

    float* qkv[3] = {(float*)p_q, (float*)p_k, (float*)p_v};
    for (int st = 0; st < NSTEPS; st++) {
        for (int l = 0; l < NLAYER; l++) {
            const size_t vd = (size_t)l*DIM, vf = (size_t)l*DFF;
            bf16* lh = whB + (size_t)l*WLAYER;
            bf16* ll = wlB + (size_t)l*WLAYER;

            ln_split_kernel<<<NROWS, 128>>>(hB, l1g + vd, l1b + vd, hnh, hnl);

            GemmArgs ga{};
            ga.s[0] = {lh + WOFF_Q, ll + WOFF_Q, bq + vd, qkv[0], nullptr, nullptr};
            ga.s[1] = {lh + WOFF_K, ll + WOFF_K, bk + vd, qkv[1], nullptr, nullptr};
            ga.s[2] = {lh + WOFF_V, ll + WOFF_V, bv + vd, qkv[2], nullptr, nullptr};
            launch_mma<0>(hnh, hnl, ga, NROWS, DIM, DIM, 3);

            attn_kernel<<<dim3(SEQ/QB, NHEAD, BATCH), 256, SMEM_ATTN>>>();

            GemmArgs go{};
            go.s[0] = {lh + WOFF_O, ll + WOFF_O, bo + vd, hB, nullptr, nullptr};
            launch_mma<1>(ohB, olB, go, NROWS, DIM, DIM, 1);

            ln_split_kernel<<<NROWS, 128>>>(hB, l2g + vd, l2b + vd, hnh, hnl);

            GemmArgs g1{};
            g1.s[0] = {lh + WOFF_1, ll + WOFF_1, b1 + vf, nullptr, mhB, mlB};
            launch_mma<2>(hnh, hnl, g1, NROWS, DFF, DIM, 1);

            GemmArgs g2{};
            g2.s[0] = {lh + WOFF_2, ll + WOFF_2, b2 + vd, hB, nullptr, nullptr};
            launch_mma<3>(mhB, mlB, g2, NROWS, DIM, DFF, 1);
        }
    }

    mean_kernel<<<BATCH*DIM/128, 128>>>();
    head_kernel<<<(BATCH*NOUT + 127)/128, 128>>>(hw, hb, out);
}